// round 16
// baseline (speedup 1.0000x reference)
#include <cuda_runtime.h>
#include <cuda_fp16.h>
#include <mma.h>
#include <stdint.h>

using namespace nvcuda;

#define NN   50000
#define EE   800000
#define DD   128
#define CC   32
#define TOT  6400000   // NN*DD
#define CAP  64        // bucket capacity per node (max degree ~40 for Poisson(16))

// ---------------- scratch (static device globals; no runtime alloc) ----------------
__device__ int      g_cnt[NN];            // zero-init at load; agg2 resets after use
__device__ int      g_bucket[NN * CAP];   // neighbor lists (12.8 MB)
__device__ float    g_dinv[NN];
__device__ uint32_t g_mask[TOT / 32];     // dropout keep-bits
__device__ __half   g_w1h[DD * DD];       // W1 pre-converted to fp16
__device__ __half2  g_h1h[NN * (DD / 2)];
__device__ __half2  g_a1h[NN * (DD / 2)]; // a1 in fp16
__device__ __half   g_h2h[NN * CC];       // h2 in fp16 (halves agg2 gather)

// ---------------- threefry (JAX partitionable, key (0,42)) ----------------
__device__ __forceinline__ uint32_t tf_bits(uint32_t c1) {
    const uint32_t ks0 = 0u;
    const uint32_t ks1 = 42u;
    const uint32_t ks2 = 0x1BD11BDAu ^ 0u ^ 42u;
    uint32_t x0 = 0u + ks0;
    uint32_t x1 = c1 + ks1;
#define TF_R(r) { x0 += x1; x1 = __funnelshift_l(x1, x1, (r)); x1 ^= x0; }
    TF_R(13) TF_R(15) TF_R(26) TF_R(6)
    x0 += ks1; x1 += ks2 + 1u;
    TF_R(17) TF_R(29) TF_R(16) TF_R(24)
    x0 += ks2; x1 += ks0 + 2u;
    TF_R(13) TF_R(15) TF_R(26) TF_R(6)
    x0 += ks0; x1 += ks1 + 3u;
    TF_R(17) TF_R(29) TF_R(16) TF_R(24)
    x0 += ks1; x1 += ks2 + 4u;
    TF_R(13) TF_R(15) TF_R(26) TF_R(6)
    x0 += ks2; x1 += ks0 + 5u;
#undef TF_R
    return x0 ^ x1;
}

__global__ void k_mask() {
    int i = blockIdx.x * blockDim.x + threadIdx.x;
    uint32_t bits = tf_bits((uint32_t)i);
    uint32_t keep = (bits & 0x80000000u) ? 0u : 1u;
    uint32_t word = __ballot_sync(0xffffffffu, keep);
    if ((threadIdx.x & 31) == 0) g_mask[i >> 5] = word;
}

// ---------------- W1 fp32 -> fp16 (once per launch; tiny) ----------------
__global__ void k_wcvt(const float* __restrict__ W) {
    int i = blockIdx.x * blockDim.x + threadIdx.x;   // grid covers 4096 float4
    float4 v = *(const float4*)(W + i * 4);
    __half2 h0 = __floats2half2_rn(v.x, v.y);
    __half2 h1 = __floats2half2_rn(v.z, v.w);
    uint2 pk;
    pk.x = *(uint32_t*)&h0;
    pk.y = *(uint32_t*)&h1;
    *(uint2*)(g_w1h + i * 4) = pk;
}

// ---------------- graph prep: single-pass bucket scatter ----------------
__global__ void k_scatter(const int* __restrict__ ei) {
    int t = blockIdx.x * blockDim.x + threadIdx.x;
    int e = t * 4;
    if (e < EE) {
        int4 s = *(const int4*)(ei + e);
        int4 d = *(const int4*)(ei + EE + e);
        int p0 = atomicAdd(&g_cnt[d.x], 1);
        int p1 = atomicAdd(&g_cnt[d.y], 1);
        int p2 = atomicAdd(&g_cnt[d.z], 1);
        int p3 = atomicAdd(&g_cnt[d.w], 1);
        g_bucket[d.x * CAP + min(p0, CAP - 1)] = s.x;
        g_bucket[d.y * CAP + min(p1, CAP - 1)] = s.y;
        g_bucket[d.z * CAP + min(p2, CAP - 1)] = s.z;
        g_bucket[d.w * CAP + min(p3, CAP - 1)] = s.w;
    }
}

__global__ void k_dinv() {
    int i = blockIdx.x * blockDim.x + threadIdx.x;
    if (i < NN) g_dinv[i] = rsqrtf((float)(g_cnt[i] + 1));
}

// ---------------- GEMM1 (fp16 wmma m16n16k16, fp32 accum): h1 = X @ W1 ------------
// block 64(M) x 128(N), BK=32, 8 warps as 4Mx2N -> warp tile 16x64.
#define XS_STRIDE 40    // halves per Xs row (32 data + 8 pad)
#define WS_STRIDE 136   // halves per Ws row (128 data + 8 pad)
__global__ void __launch_bounds__(256, 4)
k_gemm1(const float* __restrict__ X) {
    __shared__ __align__(32) __half smem_h[64 * XS_STRIDE + 32 * WS_STRIDE];  // 13.8 KB
    __half* Xs = smem_h;
    __half* Ws = smem_h + 64 * XS_STRIDE;
    int tid  = threadIdx.x;
    int lane = tid & 31;
    int warp = tid >> 5;
    int wm   = warp >> 1;
    int wn   = warp & 1;
    int m0   = blockIdx.x * 64;

    wmma::fragment<wmma::accumulator, 16, 16, 16, float> c[4];
    #pragma unroll
    for (int j = 0; j < 4; j++) wmma::fill_fragment(c[j], 0.0f);

    for (int kc = 0; kc < 128; kc += 32) {
        #pragma unroll
        for (int t = tid; t < 512; t += 256) {       // Xs: 64 rows x 8 float4 -> half
            int m = t >> 3, q = t & 7;
            int gm = m0 + m;
            float4 v = make_float4(0.f, 0.f, 0.f, 0.f);
            if (gm < NN) v = *(const float4*)(X + (size_t)gm * 128 + kc + q * 4);
            __half2 h0 = __floats2half2_rn(v.x, v.y);
            __half2 h1 = __floats2half2_rn(v.z, v.w);
            uint2 pk;
            pk.x = *(uint32_t*)&h0;
            pk.y = *(uint32_t*)&h1;
            *(uint2*)(Xs + m * XS_STRIDE + q * 4) = pk;
        }
        #pragma unroll
        for (int t = tid; t < 512; t += 256) {       // Ws: 32 rows x 16 uint4 (fp16 src)
            int k = t >> 4, q = t & 15;
            *(uint4*)(Ws + k * WS_STRIDE + q * 8) =
                *(const uint4*)(g_w1h + (size_t)(kc + k) * 128 + q * 8);
        }
        __syncthreads();
        #pragma unroll
        for (int ks = 0; ks < 32; ks += 16) {
            wmma::fragment<wmma::matrix_a, 16, 16, 16, __half, wmma::row_major> a;
            wmma::load_matrix_sync(a, Xs + (wm * 16) * XS_STRIDE + ks, XS_STRIDE);
            #pragma unroll
            for (int nt = 0; nt < 4; nt++) {
                wmma::fragment<wmma::matrix_b, 16, 16, 16, __half, wmma::row_major> b;
                wmma::load_matrix_sync(b, Ws + ks * WS_STRIDE + wn * 64 + nt * 16, WS_STRIDE);
                wmma::mma_sync(c[nt], a, b, c[nt]);
            }
        }
        __syncthreads();
    }

    // epilogue: per-warp smem staging (alias smem_h as float; 1KB/warp), fp16 out
    float* stage = ((float*)smem_h) + warp * 256;
    #pragma unroll
    for (int nt = 0; nt < 4; nt++) {
        wmma::store_matrix_sync(stage, c[nt], 16, wmma::mem_row_major);
        __syncwarp();
        int rbase = m0 + wm * 16;
        int hcol0 = wn * 32 + nt * 8;
        #pragma unroll
        for (int i = 0; i < 4; i++) {
            int idx = lane * 4 + i;
            int row = idx >> 3;
            int cp  = idx & 7;
            int gm = rbase + row;
            if (gm < NN) {
                float f0 = stage[row * 16 + cp * 2];
                float f1 = stage[row * 16 + cp * 2 + 1];
                __half2 h = __floats2half2_rn(f0, f1);
                g_h1h[(size_t)gm * 64 + hcol0 + cp] = h;
            }
        }
        __syncwarp();
    }
}

// ---------------- aggregate layer 1 + bias + relu + dropout-mask -----------
__device__ __forceinline__ void h16_fma(float4& acc, uint2 raw, float wj) {
    __half2 p0 = *(__half2*)&raw.x;
    __half2 p1 = *(__half2*)&raw.y;
    float2 f0 = __half22float2(p0);
    float2 f1 = __half22float2(p1);
    acc.x += f0.x * wj;
    acc.y += f0.y * wj;
    acc.z += f1.x * wj;
    acc.w += f1.y * wj;
}

__global__ void k_agg1(const float* __restrict__ b1) {
    int w = (blockIdx.x * blockDim.x + threadIdx.x) >> 5;
    int lane = threadIdx.x & 31;
    if (w >= NN) return;
    int v = w;
    int n = min(g_cnt[v], CAP);
    float dv = g_dinv[v];

    float4 acc = make_float4(0.f, 0.f, 0.f, 0.f);
    h16_fma(acc, *(const uint2*)(g_h1h + (size_t)v * 64 + lane * 2), dv);  // self-loop

    for (int base = 0; base < n; base += 32) {
        int take = n - base; if (take > 32) take = 32;
        int idx = 0; float wt = 0.f;
        if (lane < take) { idx = g_bucket[v * CAP + base + lane]; wt = g_dinv[idx]; }
        int j = 0;
        for (; j + 4 <= take; j += 4) {
            int   s0 = __shfl_sync(0xffffffffu, idx, j);
            int   s1 = __shfl_sync(0xffffffffu, idx, j + 1);
            int   s2 = __shfl_sync(0xffffffffu, idx, j + 2);
            int   s3 = __shfl_sync(0xffffffffu, idx, j + 3);
            float w0 = __shfl_sync(0xffffffffu, wt, j);
            float w1 = __shfl_sync(0xffffffffu, wt, j + 1);
            float w2 = __shfl_sync(0xffffffffu, wt, j + 2);
            float w3 = __shfl_sync(0xffffffffu, wt, j + 3);
            uint2 r0 = *(const uint2*)(g_h1h + (size_t)s0 * 64 + lane * 2);
            uint2 r1 = *(const uint2*)(g_h1h + (size_t)s1 * 64 + lane * 2);
            uint2 r2 = *(const uint2*)(g_h1h + (size_t)s2 * 64 + lane * 2);
            uint2 r3 = *(const uint2*)(g_h1h + (size_t)s3 * 64 + lane * 2);
            h16_fma(acc, r0, w0);
            h16_fma(acc, r1, w1);
            h16_fma(acc, r2, w2);
            h16_fma(acc, r3, w3);
        }
        for (; j < take; j++) {
            int   s  = __shfl_sync(0xffffffffu, idx, j);
            float wj = __shfl_sync(0xffffffffu, wt, j);
            h16_fma(acc, *(const uint2*)(g_h1h + (size_t)s * 64 + lane * 2), wj);
        }
    }
    float4 bb = *(const float4*)(b1 + lane * 4);
    float r[4];
    r[0] = fmaxf(acc.x * dv + bb.x, 0.f);
    r[1] = fmaxf(acc.y * dv + bb.y, 0.f);
    r[2] = fmaxf(acc.z * dv + bb.z, 0.f);
    r[3] = fmaxf(acc.w * dv + bb.w, 0.f);

    uint32_t mw = g_mask[v * 4 + (lane >> 3)];
    int bbase = (lane & 7) * 4;
    #pragma unroll
    for (int q = 0; q < 4; q++)
        r[q] = ((mw >> (bbase + q)) & 1u) ? r[q] * 2.f : 0.f;

    __half2 p0 = __floats2half2_rn(r[0], r[1]);
    __half2 p1 = __floats2half2_rn(r[2], r[3]);
    uint2 packed;
    packed.x = *(uint32_t*)&p0;
    packed.y = *(uint32_t*)&p1;
    *(uint2*)(g_a1h + (size_t)v * 64 + lane * 2) = packed;
}

// ---------------- GEMM2: h2 = a1 @ W2 (fp16 in, fp16 out) ----------------
__global__ void k_gemm2(const float* __restrict__ W) {
    __shared__ float As[32][132];
    __shared__ float Bs[32][32];
    int m0 = blockIdx.x * 128;
    int tid = threadIdx.x;
    int tx = tid & 7;
    int ty = tid >> 3;
    float acc[4][4];
    #pragma unroll
    for (int i = 0; i < 4; i++)
        #pragma unroll
        for (int j = 0; j < 4; j++) acc[i][j] = 0.f;

    for (int kc = 0; kc < 128; kc += 32) {
        #pragma unroll
        for (int t = tid; t < 1024; t += 256) {
            int m = t >> 3, q = t & 7;
            int gm = m0 + m;
            float4 v = make_float4(0.f, 0.f, 0.f, 0.f);
            if (gm < NN) {
                uint2 raw = *(const uint2*)(g_a1h + (size_t)gm * 64 + kc / 2 + q * 2);
                __half2 p0 = *(__half2*)&raw.x;
                __half2 p1 = *(__half2*)&raw.y;
                float2 f0 = __half22float2(p0);
                float2 f1 = __half22float2(p1);
                v = make_float4(f0.x, f0.y, f1.x, f1.y);
            }
            As[q * 4 + 0][m] = v.x;
            As[q * 4 + 1][m] = v.y;
            As[q * 4 + 2][m] = v.z;
            As[q * 4 + 3][m] = v.w;
        }
        if (tid < 256) {
            int k = tid >> 3, q = tid & 7;
            *(float4*)&Bs[k][q * 4] = *(const float4*)(W + (size_t)(kc + k) * 32 + q * 4);
        }
        __syncthreads();
        #pragma unroll
        for (int k = 0; k < 32; k++) {
            float4 a = *(const float4*)&As[k][ty * 4];
            float4 b = *(const float4*)&Bs[k][tx * 4];
            float av[4] = {a.x, a.y, a.z, a.w};
            float bv[4] = {b.x, b.y, b.z, b.w};
            #pragma unroll
            for (int i = 0; i < 4; i++)
                #pragma unroll
                for (int j = 0; j < 4; j++) acc[i][j] += av[i] * bv[j];
        }
        __syncthreads();
    }
    #pragma unroll
    for (int i = 0; i < 4; i++) {
        int gm = m0 + ty * 4 + i;
        if (gm < NN) {
            __half2 p0 = __floats2half2_rn(acc[i][0], acc[i][1]);
            __half2 p1 = __floats2half2_rn(acc[i][2], acc[i][3]);
            uint2 pk;
            pk.x = *(uint32_t*)&p0;
            pk.y = *(uint32_t*)&p1;
            *(uint2*)(g_h2h + (size_t)gm * 32 + tx * 4) = pk;
        }
    }
}

// ---------------- aggregate layer 2 + bias + log_softmax (+ cnt reset) ------------
__global__ void k_agg2(const float* __restrict__ b2, float* __restrict__ out) {
    int w = (blockIdx.x * blockDim.x + threadIdx.x) >> 5;
    int lane = threadIdx.x & 31;
    if (w >= NN) return;
    int v = w;
    int n = min(g_cnt[v], CAP);
    float dv = g_dinv[v];
    float acc = __half2float(g_h2h[(size_t)v * 32 + lane]) * dv;

    for (int base = 0; base < n; base += 32) {
        int take = n - base; if (take > 32) take = 32;
        int idx = 0; float wt = 0.f;
        if (lane < take) { idx = g_bucket[v * CAP + base + lane]; wt = g_dinv[idx]; }
        int j = 0;
        for (; j + 4 <= take; j += 4) {
            int   s0 = __shfl_sync(0xffffffffu, idx, j);
            int   s1 = __shfl_sync(0xffffffffu, idx, j + 1);
            int   s2 = __shfl_sync(0xffffffffu, idx, j + 2);
            int   s3 = __shfl_sync(0xffffffffu, idx, j + 3);
            float w0 = __shfl_sync(0xffffffffu, wt, j);
            float w1 = __shfl_sync(0xffffffffu, wt, j + 1);
            float w2 = __shfl_sync(0xffffffffu, wt, j + 2);
            float w3 = __shfl_sync(0xffffffffu, wt, j + 3);
            float h0 = __half2float(g_h2h[(size_t)s0 * 32 + lane]);
            float h1 = __half2float(g_h2h[(size_t)s1 * 32 + lane]);
            float h2 = __half2float(g_h2h[(size_t)s2 * 32 + lane]);
            float h3 = __half2float(g_h2h[(size_t)s3 * 32 + lane]);
            acc += h0 * w0;
            acc += h1 * w1;
            acc += h2 * w2;
            acc += h3 * w3;
        }
        for (; j < take; j++) {
            int   s  = __shfl_sync(0xffffffffu, idx, j);
            float wj = __shfl_sync(0xffffffffu, wt, j);
            acc += __half2float(g_h2h[(size_t)s * 32 + lane]) * wj;
        }
    }
    acc = acc * dv + b2[lane];
    float mx = acc;
    #pragma unroll
    for (int o = 16; o > 0; o >>= 1) mx = fmaxf(mx, __shfl_xor_sync(0xffffffffu, mx, o));
    float ex = __expf(acc - mx);
    float s = ex;
    #pragma unroll
    for (int o = 16; o > 0; o >>= 1) s += __shfl_xor_sync(0xffffffffu, s, o);
    out[(size_t)v * 32 + lane] = acc - mx - __logf(s);

    if (lane == 0) g_cnt[v] = 0;   // reset for next graph replay (last user of cnt)
}

// ---------------- launcher: 3-way fork (prep / mask / gemm1) ----------------
extern "C" void kernel_launch(void* const* d_in, const int* in_sizes, int n_in,
                              void* d_out, int out_size) {
    const float* x  = (const float*)d_in[0];
    const float* W1 = (const float*)d_in[1];
    const float* b1 = (const float*)d_in[2];
    const float* W2 = (const float*)d_in[3];
    const float* b2 = (const float*)d_in[4];
    const int*   ei = (const int*)d_in[5];
    float* out = (float*)d_out;

    static cudaStream_t s_prep = nullptr, s_mask = nullptr;
    static cudaEvent_t  ev_fork = nullptr, ev_j1 = nullptr, ev_j2 = nullptr, ev_w = nullptr;
    if (s_prep == nullptr) {
        cudaStreamCreateWithFlags(&s_prep, cudaStreamNonBlocking);
        cudaStreamCreateWithFlags(&s_mask, cudaStreamNonBlocking);
        cudaEventCreateWithFlags(&ev_fork, cudaEventDisableTiming);
        cudaEventCreateWithFlags(&ev_j1, cudaEventDisableTiming);
        cudaEventCreateWithFlags(&ev_j2, cudaEventDisableTiming);
        cudaEventCreateWithFlags(&ev_w, cudaEventDisableTiming);
    }

    cudaEventRecord(ev_fork, 0);
    cudaStreamWaitEvent(s_prep, ev_fork, 0);
    cudaStreamWaitEvent(s_mask, ev_fork, 0);

    // mask arm: W1 fp16 conversion first (gemm1 waits on it), then threefry
    k_wcvt   <<<16, 256, 0, s_mask>>>(W1);
    cudaEventRecord(ev_w, s_mask);
    k_mask   <<<TOT / 256, 256, 0, s_mask>>>();
    cudaEventRecord(ev_j2, s_mask);

    // prep arm: single-pass bucket scatter + dinv (LSU/atomic pipe)
    k_scatter<<<(EE / 4 + 255) / 256, 256, 0, s_prep>>>(ei);
    k_dinv   <<<(NN + 255) / 256, 256, 0, s_prep>>>();
    cudaEventRecord(ev_j1, s_prep);

    // main arm: fp16 wmma GEMM1 (waits only on W1 conversion)
    cudaStreamWaitEvent(0, ev_w, 0);
    k_gemm1  <<<(NN + 63) / 64, 256>>>(x);

    cudaStreamWaitEvent(0, ev_j1, 0);
    cudaStreamWaitEvent(0, ev_j2, 0);

    k_agg1   <<<(NN * 32 + 255) / 256, 256>>>(b1);
    k_gemm2  <<<(NN + 127) / 128, 256>>>(W2);
    k_agg2   <<<(NN * 32 + 255) / 256, 256>>>(b2, out);
}

// round 17
// speedup vs baseline: 1.0328x; 1.0328x over previous
#include <cuda_runtime.h>
#include <cuda_fp16.h>
#include <mma.h>
#include <stdint.h>

using namespace nvcuda;

#define NN   50000
#define EE   800000
#define DD   128
#define CC   32
#define TOT  6400000   // NN*DD
#define CAP  64        // bucket capacity per node (max degree ~40 for Poisson(16))

// ---------------- scratch (static device globals; no runtime alloc) ----------------
__device__ int      g_cnt[NN];            // zero-init at load; agg2 resets after use
__device__ int      g_bucket[NN * CAP];   // neighbor lists (12.8 MB)
__device__ float    g_dinv[NN];
__device__ uint32_t g_mask[TOT / 32];     // dropout keep-bits
__device__ __half2  g_h1h[NN * (DD / 2)];
__device__ __half2  g_a1h[NN * (DD / 2)]; // a1 in fp16
__device__ __half   g_h2h[NN * CC];       // h2 in fp16 (halves agg2 gather)

// ---------------- threefry (JAX partitionable, key (0,42)) ----------------
__device__ __forceinline__ uint32_t tf_bits(uint32_t c1) {
    const uint32_t ks0 = 0u;
    const uint32_t ks1 = 42u;
    const uint32_t ks2 = 0x1BD11BDAu ^ 0u ^ 42u;
    uint32_t x0 = 0u + ks0;
    uint32_t x1 = c1 + ks1;
#define TF_R(r) { x0 += x1; x1 = __funnelshift_l(x1, x1, (r)); x1 ^= x0; }
    TF_R(13) TF_R(15) TF_R(26) TF_R(6)
    x0 += ks1; x1 += ks2 + 1u;
    TF_R(17) TF_R(29) TF_R(16) TF_R(24)
    x0 += ks2; x1 += ks0 + 2u;
    TF_R(13) TF_R(15) TF_R(26) TF_R(6)
    x0 += ks0; x1 += ks1 + 3u;
    TF_R(17) TF_R(29) TF_R(16) TF_R(24)
    x0 += ks1; x1 += ks2 + 4u;
    TF_R(13) TF_R(15) TF_R(26) TF_R(6)
    x0 += ks2; x1 += ks0 + 5u;
#undef TF_R
    return x0 ^ x1;
}

__global__ void k_mask() {
    int i = blockIdx.x * blockDim.x + threadIdx.x;
    uint32_t bits = tf_bits((uint32_t)i);
    uint32_t keep = (bits & 0x80000000u) ? 0u : 1u;
    uint32_t word = __ballot_sync(0xffffffffu, keep);
    if ((threadIdx.x & 31) == 0) g_mask[i >> 5] = word;
}

// ---------------- graph prep: single-pass bucket scatter ----------------
__global__ void k_scatter(const int* __restrict__ ei) {
    int t = blockIdx.x * blockDim.x + threadIdx.x;
    int e = t * 4;
    if (e < EE) {
        int4 s = *(const int4*)(ei + e);
        int4 d = *(const int4*)(ei + EE + e);
        int p0 = atomicAdd(&g_cnt[d.x], 1);
        int p1 = atomicAdd(&g_cnt[d.y], 1);
        int p2 = atomicAdd(&g_cnt[d.z], 1);
        int p3 = atomicAdd(&g_cnt[d.w], 1);
        g_bucket[d.x * CAP + min(p0, CAP - 1)] = s.x;
        g_bucket[d.y * CAP + min(p1, CAP - 1)] = s.y;
        g_bucket[d.z * CAP + min(p2, CAP - 1)] = s.z;
        g_bucket[d.w * CAP + min(p3, CAP - 1)] = s.w;
    }
}

__global__ void k_dinv() {
    int i = blockIdx.x * blockDim.x + threadIdx.x;
    if (i < NN) g_dinv[i] = rsqrtf((float)(g_cnt[i] + 1));
}

// ---------------- GEMM1 (fp16 wmma m16n16k16, fp32 accum): h1 = X @ W1 ------------
// block 64(M) x 128(N), BK=64 (2 kc rounds), 8 warps as 4Mx2N -> warp tile 16x64.
#define XS_STRIDE 72    // halves per Xs row (64 data + 8 pad)
#define WS_STRIDE 136   // halves per Ws row (128 data + 8 pad)
__global__ void __launch_bounds__(256, 4)
k_gemm1(const float* __restrict__ X, const float* __restrict__ W) {
    __shared__ __align__(32) __half smem_h[64 * XS_STRIDE + 64 * WS_STRIDE];  // 26.6 KB
    __half* Xs = smem_h;                      // [64][XS_STRIDE]
    __half* Ws = smem_h + 64 * XS_STRIDE;     // [64][WS_STRIDE]
    int tid  = threadIdx.x;
    int lane = tid & 31;
    int warp = tid >> 5;
    int wm   = warp >> 1;
    int wn   = warp & 1;
    int m0   = blockIdx.x * 64;

    wmma::fragment<wmma::accumulator, 16, 16, 16, float> c[4];
    #pragma unroll
    for (int j = 0; j < 4; j++) wmma::fill_fragment(c[j], 0.0f);

    for (int kc = 0; kc < 128; kc += 64) {
        #pragma unroll
        for (int t = tid; t < 1024; t += 256) {      // Xs: 64 rows x 16 float4 -> half
            int m = t >> 4, q = t & 15;
            int gm = m0 + m;
            float4 v = make_float4(0.f, 0.f, 0.f, 0.f);
            if (gm < NN) v = *(const float4*)(X + (size_t)gm * 128 + kc + q * 4);
            __half2 h0 = __floats2half2_rn(v.x, v.y);
            __half2 h1 = __floats2half2_rn(v.z, v.w);
            uint2 pk;
            pk.x = *(uint32_t*)&h0;
            pk.y = *(uint32_t*)&h1;
            *(uint2*)(Xs + m * XS_STRIDE + q * 4) = pk;
        }
        #pragma unroll
        for (int t = tid; t < 2048; t += 256) {      // Ws: 64 rows x 32 float4 -> half
            int k = t >> 5, q = t & 31;
            float4 v = *(const float4*)(W + (size_t)(kc + k) * 128 + q * 4);
            __half2 h0 = __floats2half2_rn(v.x, v.y);
            __half2 h1 = __floats2half2_rn(v.z, v.w);
            uint2 pk;
            pk.x = *(uint32_t*)&h0;
            pk.y = *(uint32_t*)&h1;
            *(uint2*)(Ws + k * WS_STRIDE + q * 4) = pk;
        }
        __syncthreads();
        #pragma unroll
        for (int ks = 0; ks < 64; ks += 16) {
            wmma::fragment<wmma::matrix_a, 16, 16, 16, __half, wmma::row_major> a;
            wmma::load_matrix_sync(a, Xs + (wm * 16) * XS_STRIDE + ks, XS_STRIDE);
            #pragma unroll
            for (int nt = 0; nt < 4; nt++) {
                wmma::fragment<wmma::matrix_b, 16, 16, 16, __half, wmma::row_major> b;
                wmma::load_matrix_sync(b, Ws + ks * WS_STRIDE + wn * 64 + nt * 16, WS_STRIDE);
                wmma::mma_sync(c[nt], a, b, c[nt]);
            }
        }
        __syncthreads();
    }

    // epilogue: per-warp smem staging (alias smem_h as float; 1KB/warp), fp16 out
    float* stage = ((float*)smem_h) + warp * 256;
    #pragma unroll
    for (int nt = 0; nt < 4; nt++) {
        wmma::store_matrix_sync(stage, c[nt], 16, wmma::mem_row_major);
        __syncwarp();
        int rbase = m0 + wm * 16;
        int hcol0 = wn * 32 + nt * 8;
        #pragma unroll
        for (int i = 0; i < 4; i++) {
            int idx = lane * 4 + i;
            int row = idx >> 3;
            int cp  = idx & 7;
            int gm = rbase + row;
            if (gm < NN) {
                float f0 = stage[row * 16 + cp * 2];
                float f1 = stage[row * 16 + cp * 2 + 1];
                __half2 h = __floats2half2_rn(f0, f1);
                g_h1h[(size_t)gm * 64 + hcol0 + cp] = h;
            }
        }
        __syncwarp();
    }
}

// ---------------- aggregate layer 1 + bias + relu + dropout-mask -----------
__device__ __forceinline__ void h16_fma(float4& acc, uint2 raw, float wj) {
    __half2 p0 = *(__half2*)&raw.x;
    __half2 p1 = *(__half2*)&raw.y;
    float2 f0 = __half22float2(p0);
    float2 f1 = __half22float2(p1);
    acc.x += f0.x * wj;
    acc.y += f0.y * wj;
    acc.z += f1.x * wj;
    acc.w += f1.y * wj;
}

__global__ void k_agg1(const float* __restrict__ b1) {
    int w = (blockIdx.x * blockDim.x + threadIdx.x) >> 5;
    int lane = threadIdx.x & 31;
    if (w >= NN) return;
    int v = w;
    int n = min(g_cnt[v], CAP);
    float dv = g_dinv[v];

    float4 acc = make_float4(0.f, 0.f, 0.f, 0.f);
    h16_fma(acc, *(const uint2*)(g_h1h + (size_t)v * 64 + lane * 2), dv);  // self-loop

    for (int base = 0; base < n; base += 32) {
        int take = n - base; if (take > 32) take = 32;
        int idx = 0; float wt = 0.f;
        if (lane < take) { idx = g_bucket[v * CAP + base + lane]; wt = g_dinv[idx]; }
        int j = 0;
        for (; j + 4 <= take; j += 4) {
            int   s0 = __shfl_sync(0xffffffffu, idx, j);
            int   s1 = __shfl_sync(0xffffffffu, idx, j + 1);
            int   s2 = __shfl_sync(0xffffffffu, idx, j + 2);
            int   s3 = __shfl_sync(0xffffffffu, idx, j + 3);
            float w0 = __shfl_sync(0xffffffffu, wt, j);
            float w1 = __shfl_sync(0xffffffffu, wt, j + 1);
            float w2 = __shfl_sync(0xffffffffu, wt, j + 2);
            float w3 = __shfl_sync(0xffffffffu, wt, j + 3);
            uint2 r0 = *(const uint2*)(g_h1h + (size_t)s0 * 64 + lane * 2);
            uint2 r1 = *(const uint2*)(g_h1h + (size_t)s1 * 64 + lane * 2);
            uint2 r2 = *(const uint2*)(g_h1h + (size_t)s2 * 64 + lane * 2);
            uint2 r3 = *(const uint2*)(g_h1h + (size_t)s3 * 64 + lane * 2);
            h16_fma(acc, r0, w0);
            h16_fma(acc, r1, w1);
            h16_fma(acc, r2, w2);
            h16_fma(acc, r3, w3);
        }
        for (; j < take; j++) {
            int   s  = __shfl_sync(0xffffffffu, idx, j);
            float wj = __shfl_sync(0xffffffffu, wt, j);
            h16_fma(acc, *(const uint2*)(g_h1h + (size_t)s * 64 + lane * 2), wj);
        }
    }
    float4 bb = *(const float4*)(b1 + lane * 4);
    float r[4];
    r[0] = fmaxf(acc.x * dv + bb.x, 0.f);
    r[1] = fmaxf(acc.y * dv + bb.y, 0.f);
    r[2] = fmaxf(acc.z * dv + bb.z, 0.f);
    r[3] = fmaxf(acc.w * dv + bb.w, 0.f);

    uint32_t mw = g_mask[v * 4 + (lane >> 3)];
    int bbase = (lane & 7) * 4;
    #pragma unroll
    for (int q = 0; q < 4; q++)
        r[q] = ((mw >> (bbase + q)) & 1u) ? r[q] * 2.f : 0.f;

    __half2 p0 = __floats2half2_rn(r[0], r[1]);
    __half2 p1 = __floats2half2_rn(r[2], r[3]);
    uint2 packed;
    packed.x = *(uint32_t*)&p0;
    packed.y = *(uint32_t*)&p1;
    *(uint2*)(g_a1h + (size_t)v * 64 + lane * 2) = packed;
}

// ---------------- GEMM2: h2 = a1 @ W2 (fp16 in, fp16 out) ----------------
__global__ void k_gemm2(const float* __restrict__ W) {
    __shared__ float As[32][132];
    __shared__ float Bs[32][32];
    int m0 = blockIdx.x * 128;
    int tid = threadIdx.x;
    int tx = tid & 7;
    int ty = tid >> 3;
    float acc[4][4];
    #pragma unroll
    for (int i = 0; i < 4; i++)
        #pragma unroll
        for (int j = 0; j < 4; j++) acc[i][j] = 0.f;

    for (int kc = 0; kc < 128; kc += 32) {
        #pragma unroll
        for (int t = tid; t < 1024; t += 256) {
            int m = t >> 3, q = t & 7;
            int gm = m0 + m;
            float4 v = make_float4(0.f, 0.f, 0.f, 0.f);
            if (gm < NN) {
                uint2 raw = *(const uint2*)(g_a1h + (size_t)gm * 64 + kc / 2 + q * 2);
                __half2 p0 = *(__half2*)&raw.x;
                __half2 p1 = *(__half2*)&raw.y;
                float2 f0 = __half22float2(p0);
                float2 f1 = __half22float2(p1);
                v = make_float4(f0.x, f0.y, f1.x, f1.y);
            }
            As[q * 4 + 0][m] = v.x;
            As[q * 4 + 1][m] = v.y;
            As[q * 4 + 2][m] = v.z;
            As[q * 4 + 3][m] = v.w;
        }
        if (tid < 256) {
            int k = tid >> 3, q = tid & 7;
            *(float4*)&Bs[k][q * 4] = *(const float4*)(W + (size_t)(kc + k) * 32 + q * 4);
        }
        __syncthreads();
        #pragma unroll
        for (int k = 0; k < 32; k++) {
            float4 a = *(const float4*)&As[k][ty * 4];
            float4 b = *(const float4*)&Bs[k][tx * 4];
            float av[4] = {a.x, a.y, a.z, a.w};
            float bv[4] = {b.x, b.y, b.z, b.w};
            #pragma unroll
            for (int i = 0; i < 4; i++)
                #pragma unroll
                for (int j = 0; j < 4; j++) acc[i][j] += av[i] * bv[j];
        }
        __syncthreads();
    }
    #pragma unroll
    for (int i = 0; i < 4; i++) {
        int gm = m0 + ty * 4 + i;
        if (gm < NN) {
            __half2 p0 = __floats2half2_rn(acc[i][0], acc[i][1]);
            __half2 p1 = __floats2half2_rn(acc[i][2], acc[i][3]);
            uint2 pk;
            pk.x = *(uint32_t*)&p0;
            pk.y = *(uint32_t*)&p1;
            *(uint2*)(g_h2h + (size_t)gm * 32 + tx * 4) = pk;
        }
    }
}

// ---------------- aggregate layer 2 + bias + log_softmax (+ cnt reset) ------------
__global__ void k_agg2(const float* __restrict__ b2, float* __restrict__ out) {
    int w = (blockIdx.x * blockDim.x + threadIdx.x) >> 5;
    int lane = threadIdx.x & 31;
    if (w >= NN) return;
    int v = w;
    int n = min(g_cnt[v], CAP);
    float dv = g_dinv[v];
    float acc = __half2float(g_h2h[(size_t)v * 32 + lane]) * dv;

    for (int base = 0; base < n; base += 32) {
        int take = n - base; if (take > 32) take = 32;
        int idx = 0; float wt = 0.f;
        if (lane < take) { idx = g_bucket[v * CAP + base + lane]; wt = g_dinv[idx]; }
        int j = 0;
        for (; j + 4 <= take; j += 4) {
            int   s0 = __shfl_sync(0xffffffffu, idx, j);
            int   s1 = __shfl_sync(0xffffffffu, idx, j + 1);
            int   s2 = __shfl_sync(0xffffffffu, idx, j + 2);
            int   s3 = __shfl_sync(0xffffffffu, idx, j + 3);
            float w0 = __shfl_sync(0xffffffffu, wt, j);
            float w1 = __shfl_sync(0xffffffffu, wt, j + 1);
            float w2 = __shfl_sync(0xffffffffu, wt, j + 2);
            float w3 = __shfl_sync(0xffffffffu, wt, j + 3);
            float h0 = __half2float(g_h2h[(size_t)s0 * 32 + lane]);
            float h1 = __half2float(g_h2h[(size_t)s1 * 32 + lane]);
            float h2 = __half2float(g_h2h[(size_t)s2 * 32 + lane]);
            float h3 = __half2float(g_h2h[(size_t)s3 * 32 + lane]);
            acc += h0 * w0;
            acc += h1 * w1;
            acc += h2 * w2;
            acc += h3 * w3;
        }
        for (; j < take; j++) {
            int   s  = __shfl_sync(0xffffffffu, idx, j);
            float wj = __shfl_sync(0xffffffffu, wt, j);
            acc += __half2float(g_h2h[(size_t)s * 32 + lane]) * wj;
        }
    }
    acc = acc * dv + b2[lane];
    float mx = acc;
    #pragma unroll
    for (int o = 16; o > 0; o >>= 1) mx = fmaxf(mx, __shfl_xor_sync(0xffffffffu, mx, o));
    float ex = __expf(acc - mx);
    float s = ex;
    #pragma unroll
    for (int o = 16; o > 0; o >>= 1) s += __shfl_xor_sync(0xffffffffu, s, o);
    out[(size_t)v * 32 + lane] = acc - mx - __logf(s);

    if (lane == 0) g_cnt[v] = 0;   // reset for next graph replay (last user of cnt)
}

// ---------------- launcher: 3-way fork (prep / mask / gemm1) ----------------
extern "C" void kernel_launch(void* const* d_in, const int* in_sizes, int n_in,
                              void* d_out, int out_size) {
    const float* x  = (const float*)d_in[0];
    const float* W1 = (const float*)d_in[1];
    const float* b1 = (const float*)d_in[2];
    const float* W2 = (const float*)d_in[3];
    const float* b2 = (const float*)d_in[4];
    const int*   ei = (const int*)d_in[5];
    float* out = (float*)d_out;

    static cudaStream_t s_prep = nullptr, s_mask = nullptr;
    static cudaEvent_t  ev_fork = nullptr, ev_j1 = nullptr, ev_j2 = nullptr;
    if (s_prep == nullptr) {
        cudaStreamCreateWithFlags(&s_prep, cudaStreamNonBlocking);
        cudaStreamCreateWithFlags(&s_mask, cudaStreamNonBlocking);
        cudaEventCreateWithFlags(&ev_fork, cudaEventDisableTiming);
        cudaEventCreateWithFlags(&ev_j1, cudaEventDisableTiming);
        cudaEventCreateWithFlags(&ev_j2, cudaEventDisableTiming);
    }

    cudaEventRecord(ev_fork, 0);
    cudaStreamWaitEvent(s_prep, ev_fork, 0);
    cudaStreamWaitEvent(s_mask, ev_fork, 0);

    // prep arm: single-pass bucket scatter + dinv (LSU/atomic pipe)
    k_scatter<<<(EE / 4 + 255) / 256, 256, 0, s_prep>>>(ei);
    k_dinv   <<<(NN + 255) / 256, 256, 0, s_prep>>>();
    cudaEventRecord(ev_j1, s_prep);

    // mask arm: threefry (ALU pipe)
    k_mask   <<<TOT / 256, 256, 0, s_mask>>>();
    cudaEventRecord(ev_j2, s_mask);

    // main arm: fp16 wmma GEMM1, BK=64 (W converted in fill; no extra kernel)
    k_gemm1  <<<(NN + 63) / 64, 256>>>(x, W1);

    cudaStreamWaitEvent(0, ev_j1, 0);
    cudaStreamWaitEvent(0, ev_j2, 0);

    k_agg1   <<<(NN * 32 + 255) / 256, 256>>>(b1);
    k_gemm2  <<<(NN + 127) / 128, 256>>>(W2);
    k_agg2   <<<(NN * 32 + 255) / 256, 256>>>(b2, out);
}